// round 4
// baseline (speedup 1.0000x reference)
#include <cuda_runtime.h>

#define BATCH   1024
#define TSTEPS  100
#define L0      30
#define C1      16
#define L1      24
#define K1      7
#define C2      32
#define L2      20
#define K2      5
#define C3      64
#define L3      18
#define K3      3
#define F1      1152   // 64*18
#define H1      256
#define NC      10

#define NTHREADS 256
#define S1W      18     // padded s1 row stride (floats) to avoid STS.64 bank conflicts

typedef unsigned long long u64;

// Transposed fc1 weights: fw1T[i*H1 + j] = fw1[j*F1 + i]
__device__ __align__(16) float g_fw1T[F1 * H1];

__global__ void transpose_fw1_kernel(const float* __restrict__ fw1) {
    int idx = blockIdx.x * blockDim.x + threadIdx.x;
    if (idx < H1 * F1) {
        int j = idx / F1;
        int i = idx - j * F1;
        g_fw1T[i * H1 + j] = fw1[idx];
    }
}

// ---- f32x2 helpers ----
__device__ __forceinline__ u64 ffma2(u64 a, u64 b, u64 c) {
    u64 d; asm("fma.rn.f32x2 %0, %1, %2, %3;" : "=l"(d) : "l"(a), "l"(b), "l"(c)); return d;
}
__device__ __forceinline__ u64 fadd2(u64 a, u64 b) {
    u64 d; asm("add.rn.f32x2 %0, %1, %2;" : "=l"(d) : "l"(a), "l"(b)); return d;
}
__device__ __forceinline__ u64 pack2(float lo, float hi) {
    u64 r; asm("mov.b64 %0, {%1, %2};" : "=l"(r) : "f"(lo), "f"(hi)); return r;
}
__device__ __forceinline__ void unpack2(u64 v, float& lo, float& hi) {
    asm("mov.b64 {%0, %1}, %2;" : "=f"(lo), "=f"(hi) : "l"(v));
}
__device__ __forceinline__ u64 lds64(const float* p) { return *(const u64*)p; }

// LIF: reset from PREVIOUS mem (subtract), spike on new mem.
// No FMA contraction: match reference op sequence 0.9*m + h - reset.
__device__ __forceinline__ float lif_new_mem(float m_old, float h) {
    float reset = (m_old > 1.0f) ? 1.0f : 0.0f;
    return __fadd_rn(__fadd_rn(__fmul_rn(0.9f, m_old), h), -reset);
}

// smem layout (words): sw2p 2560 | sw3p 6144 | sx 3000 | s1 432 | s2 640 | s4 256 | mask3 64
#define OFF_SW2P 0
#define OFF_SW3P 2560
#define OFF_SX   8704
#define OFF_S1   11704
#define OFF_S2   12136
#define OFF_S4   12776
#define OFF_MSK  13032
#define SMEM_WORDS 13096
#define SMEM_BYTES (SMEM_WORDS * 4)

__global__ __launch_bounds__(NTHREADS, 3)
void snn_kernel(const float* __restrict__ x,
                const float* __restrict__ w1, const float* __restrict__ b1,
                const float* __restrict__ w2, const float* __restrict__ b2,
                const float* __restrict__ w3, const float* __restrict__ b3,
                const float* __restrict__ fb1,
                const float* __restrict__ fw2, const float* __restrict__ fb2,
                float* __restrict__ out)
{
    extern __shared__ float smem[];
    float* sw2p = smem + OFF_SW2P;   // [((p*5+k)*32+co)*2+e]
    float* sw3p = smem + OFF_SW3P;   // [((p*3+k)*64+co)*2+e]
    float* sx   = smem + OFF_SX;     // [t][l]  (3000)
    float* s1   = smem + OFF_S1;     // [l][S1W] pairs at 2*cp
    float* s2   = smem + OFF_S2;     // [l][32]
    float* s4   = smem + OFF_S4;     // [256]
    unsigned* mask3 = (unsigned*)(smem + OFF_MSK);  // [64]

    const int tid  = threadIdx.x;
    const int b    = blockIdx.x;
    const int lane = tid & 31;
    const int warp = tid >> 5;

    // ---- pack conv2/conv3 weights into smem ----
    for (int i = tid; i < C2 * C1 * K2; i += NTHREADS) {
        int co = i / (C1 * K2);
        int r = i - co * (C1 * K2);
        int ci = r / K2, k = r - ci * K2;
        sw2p[(((ci >> 1) * K2 + k) * C2 + co) * 2 + (ci & 1)] = w2[i];
    }
    for (int i = tid; i < C3 * C2 * K3; i += NTHREADS) {
        int co = i / (C2 * K3);
        int r = i - co * (C2 * K3);
        int ci = r / K3, k = r - ci * K3;
        sw3p[(((ci >> 1) * K3 + k) * C3 + co) * 2 + (ci & 1)] = w3[i];
    }
    // x -> smem transposed: sx[t*30 + l] = x[b,0,l,t]  (global reads coalesced over t)
    for (int i = tid; i < L0 * TSTEPS; i += NTHREADS) {
        int l = i / TSTEPS, tt = i - l * TSTEPS;
        sx[tt * L0 + l] = x[b * (L0 * TSTEPS) + i];
    }

    // ---- per-thread register state (membranes, invariant weights/biases) ----
    // conv1: every warp owns channel pair cp = warp; lanes 0..23 = positions
    const int cp = warp;
    u64 w1r[K1];
    u64 b1p = 0, m1r = 0;
    if (lane < 24) {
        #pragma unroll
        for (int k = 0; k < K1; k++)
            w1r[k] = pack2(w1[(2 * cp) * K1 + k], w1[(2 * cp + 1) * K1 + k]);
        b1p = pack2(b1[2 * cp], b1[2 * cp + 1]);
    }
    // conv2 (warps 4-7): co = lane, l0 = (warp-4)*5
    float b2r = 0.0f, m2r[5];
    #pragma unroll
    for (int q = 0; q < 5; q++) m2r[q] = 0.0f;
    if (warp >= 4) b2r = b2[lane];
    // conv3 (warps 0-3): co = (warp&1)*32+lane, l0 = (warp>>1)*9
    const int co3 = ((warp & 1) << 5) + lane;
    float b3r = 0.0f, m3r[9];
    #pragma unroll
    for (int q = 0; q < 9; q++) m3r[q] = 0.0f;
    if (warp < 4) b3r = b3[co3];
    // fc1 (warps 4-7): j2 = tid-128
    const int j2 = tid - 128;
    u64 fb1p = 0;
    float m4a = 0.0f, m4b = 0.0f;
    if (warp >= 4) fb1p = *(const u64*)(fb1 + 2 * j2);
    // fc2 (warps 0-3): j = warp + 4*i
    float fb2r[3], m5r[3];
    #pragma unroll
    for (int i = 0; i < 3; i++) { fb2r[i] = 0.0f; m5r[i] = 0.0f; }
    if (warp < 4 && lane == 0) {
        #pragma unroll
        for (int i = 0; i < 3; i++) {
            int j = warp + 4 * i;
            if (j < NC) fb2r[i] = fb2[j];
        }
    }
    __syncthreads();

    for (int t = 0; t < TSTEPS; t++) {
        // ======== conv1 (all warps; lanes 24-31 clear mask3) ========
        if (lane < 24) {
            const float* xr = sx + t * L0 + lane;
            u64 acc = b1p;
            #pragma unroll
            for (int k = 0; k < K1; k++) {
                float xv = xr[k];
                acc = ffma2(w1r[k], pack2(xv, xv), acc);
            }
            float he, ho, me, mo;
            unpack2(acc, he, ho);
            unpack2(m1r, me, mo);
            float mne = lif_new_mem(me, he);
            float mno = lif_new_mem(mo, ho);
            m1r = pack2(mne, mno);
            *(u64*)(s1 + lane * S1W + 2 * cp) =
                pack2((mne > 1.0f) ? 1.0f : 0.0f, (mno > 1.0f) ? 1.0f : 0.0f);
        } else {
            mask3[(warp << 3) + (lane - 24)] = 0u;
        }
        __syncthreads();   // S1

        // ======== conv2 (warps 4-7): co=lane, 5 l each ========
        if (warp >= 4) {
            const int co = lane;
            const int l0 = (warp - 4) * 5;
            u64 acc[5];
            u64 binit = pack2(b2r, 0.0f);
            #pragma unroll
            for (int q = 0; q < 5; q++) acc[q] = binit;
            for (int p = 0; p < 8; p++) {
                const float* wb = sw2p + (p * (K2 * C2) + co) * 2;
                u64 wv0 = lds64(wb);
                u64 wv1 = lds64(wb + 64);
                u64 wv2 = lds64(wb + 128);
                u64 wv3 = lds64(wb + 192);
                u64 wv4 = lds64(wb + 256);
                const float* sp = s1 + l0 * S1W + 2 * p;
                #pragma unroll
                for (int d = 0; d < 9; d++) {
                    u64 sv = lds64(sp + d * S1W);
                    if (d <= 4)           acc[d]     = ffma2(wv0, sv, acc[d]);
                    if (d >= 1 && d <= 5) acc[d - 1] = ffma2(wv1, sv, acc[d - 1]);
                    if (d >= 2 && d <= 6) acc[d - 2] = ffma2(wv2, sv, acc[d - 2]);
                    if (d >= 3 && d <= 7) acc[d - 3] = ffma2(wv3, sv, acc[d - 3]);
                    if (d >= 4)           acc[d - 4] = ffma2(wv4, sv, acc[d - 4]);
                }
            }
            #pragma unroll
            for (int q = 0; q < 5; q++) {
                float lo, hi; unpack2(acc[q], lo, hi);
                float h = __fadd_rn(lo, hi);
                float mn = lif_new_mem(m2r[q], h);
                m2r[q] = mn;
                s2[(l0 + q) * C2 + co] = (mn > 1.0f) ? 1.0f : 0.0f;
            }
        }
        __syncthreads();   // S2

        // ======== conv3 (warps 0-3): co3, 9 l each ========
        if (warp < 4) {
            const int l0 = (warp >> 1) * 9;
            u64 acc[9];
            u64 binit = pack2(b3r, 0.0f);
            #pragma unroll
            for (int q = 0; q < 9; q++) acc[q] = binit;
            for (int p = 0; p < 16; p++) {
                const float* wb = sw3p + (p * (K3 * C3) + co3) * 2;
                u64 wv0 = lds64(wb);
                u64 wv1 = lds64(wb + 128);
                u64 wv2 = lds64(wb + 256);
                const float* sp = s2 + l0 * C2 + 2 * p;
                #pragma unroll
                for (int d = 0; d < 11; d++) {
                    u64 sv = lds64(sp + d * C2);
                    if (d <= 8)           acc[d]     = ffma2(wv0, sv, acc[d]);
                    if (d >= 1 && d <= 9) acc[d - 1] = ffma2(wv1, sv, acc[d - 1]);
                    if (d >= 2)           acc[d - 2] = ffma2(wv2, sv, acc[d - 2]);
                }
            }
            unsigned bits = 0;
            #pragma unroll
            for (int q = 0; q < 9; q++) {
                float lo, hi; unpack2(acc[q], lo, hi);
                float h = __fadd_rn(lo, hi);
                float mn = lif_new_mem(m3r[q], h);
                m3r[q] = mn;
                if (mn > 1.0f) bits |= 1u << q;
            }
            if (bits) atomicOr(&mask3[co3], bits << l0);
        }
        __syncthreads();   // S3

        // ======== fc1 (warps 4-7): sparse gather, float2 per thread ========
        if (warp >= 4) {
            u64 acc = fb1p;
            #pragma unroll 4
            for (int r = 0; r < C3; r++) {
                unsigned m = mask3[r];   // uniform broadcast
                const float* base = g_fw1T + r * (L3 * H1) + 2 * j2;
                while (m) {
                    int l = __ffs(m) - 1;
                    m &= m - 1;
                    acc = fadd2(acc, *(const u64*)(base + l * H1));
                }
            }
            float lo, hi; unpack2(acc, lo, hi);
            float mn0 = lif_new_mem(m4a, lo);
            float mn1 = lif_new_mem(m4b, hi);
            m4a = mn0; m4b = mn1;
            *(u64*)(s4 + 2 * j2) =
                pack2((mn0 > 1.0f) ? 1.0f : 0.0f, (mn1 > 1.0f) ? 1.0f : 0.0f);
        }
        __syncthreads();   // S4

        // ======== fc2 (warps 0-3) + output ========
        if (warp < 4) {
            #pragma unroll
            for (int i = 0; i < 3; i++) {
                int j = warp + 4 * i;
                if (j < NC) {
                    float acc = 0.0f;
                    #pragma unroll
                    for (int q = 0; q < 8; q++) {
                        int ii = lane + 32 * q;
                        acc = fmaf(__ldg(&fw2[j * H1 + ii]), s4[ii], acc);
                    }
                    #pragma unroll
                    for (int o = 16; o > 0; o >>= 1)
                        acc += __shfl_down_sync(0xffffffff, acc, o);
                    if (lane == 0) {
                        acc += fb2r[i];
                        float mn = lif_new_mem(m5r[i], acc);
                        m5r[i] = mn;
                        out[(t * BATCH + b) * NC + j] = (mn > 1.0f) ? 1.0f : 0.0f;
                    }
                }
            }
        }
        // no sync needed: next S1 orders fc2 against the following timestep
    }
}

extern "C" void kernel_launch(void* const* d_in, const int* in_sizes, int n_in,
                              void* d_out, int out_size) {
    const float* x   = (const float*)d_in[0];
    const float* w1  = (const float*)d_in[1];
    const float* b1  = (const float*)d_in[2];
    const float* w2  = (const float*)d_in[3];
    const float* b2  = (const float*)d_in[4];
    const float* w3  = (const float*)d_in[5];
    const float* b3  = (const float*)d_in[6];
    const float* fw1 = (const float*)d_in[7];
    const float* fb1 = (const float*)d_in[8];
    const float* fw2 = (const float*)d_in[9];
    const float* fb2 = (const float*)d_in[10];
    float* out = (float*)d_out;

    cudaFuncSetAttribute(snn_kernel, cudaFuncAttributeMaxDynamicSharedMemorySize, SMEM_BYTES);

    transpose_fw1_kernel<<<(H1 * F1 + 255) / 256, 256>>>(fw1);
    snn_kernel<<<BATCH, NTHREADS, SMEM_BYTES>>>(x, w1, b1, w2, b2, w3, b3,
                                                fb1, fw2, fb2, out);
}

// round 5
// speedup vs baseline: 1.1355x; 1.1355x over previous
#include <cuda_runtime.h>

#define BATCH   1024
#define TSTEPS  100
#define L0      30
#define C1      16
#define L1      24
#define K1      7
#define C2      32
#define L2      20
#define K2      5
#define C3      64
#define L3      18
#define K3      3
#define F1      1152   // 64*18
#define H1      256
#define NC      10

#define NTHREADS 256
#define S1W      18

typedef unsigned long long u64;

// Transposed fc1 weights: fw1T[i*H1 + j] = fw1[j*F1 + i]
__device__ __align__(16) float g_fw1T[F1 * H1];

__global__ void transpose_fw1_kernel(const float* __restrict__ fw1) {
    int idx = blockIdx.x * blockDim.x + threadIdx.x;
    if (idx < H1 * F1) {
        int j = idx / F1;
        int i = idx - j * F1;
        g_fw1T[i * H1 + j] = fw1[idx];
    }
}

// ---- f32x2 helpers ----
__device__ __forceinline__ u64 ffma2(u64 a, u64 b, u64 c) {
    u64 d; asm("fma.rn.f32x2 %0, %1, %2, %3;" : "=l"(d) : "l"(a), "l"(b), "l"(c)); return d;
}
__device__ __forceinline__ u64 fadd2(u64 a, u64 b) {
    u64 d; asm("add.rn.f32x2 %0, %1, %2;" : "=l"(d) : "l"(a), "l"(b)); return d;
}
__device__ __forceinline__ u64 pack2(float lo, float hi) {
    u64 r; asm("mov.b64 %0, {%1, %2};" : "=l"(r) : "f"(lo), "f"(hi)); return r;
}
__device__ __forceinline__ void unpack2(u64 v, float& lo, float& hi) {
    asm("mov.b64 {%0, %1}, %2;" : "=f"(lo), "=f"(hi) : "l"(v));
}
__device__ __forceinline__ u64 lds64(const float* p) { return *(const u64*)p; }

// LIF: reset from PREVIOUS mem (subtract), spike on new mem.
__device__ __forceinline__ float lif_new_mem(float m_old, float h) {
    float reset = (m_old > 1.0f) ? 1.0f : 0.0f;
    return __fadd_rn(__fadd_rn(__fmul_rn(0.9f, m_old), h), -reset);
}

// smem layout (words)
#define OFF_SW1P 0         // 112: [(k*8+cp)*2+e]
#define OFF_SB1P 112       // 16
#define OFF_SW2P 128       // 2560: [((p*5+k)*32+co)*2+e]
#define OFF_SW3P 2688      // 6144: [((p*3+k)*64+co)*2+e]
#define OFF_SX   8832      // 3000: [t][l]
#define OFF_S1   11832     // 2*432: [buf][l*18+2cp]
#define OFF_S2   12696     // 2*640: [buf][l*32+co]
#define OFF_S4   13976     // 2*256
#define OFF_MSK  14488     // 2*192: [buf][third*64+co]
#define S1SZ 432
#define S2SZ 640
#define S4SZ 256
#define MSKSZ 192
#define SMEM_WORDS 14872
#define SMEM_BYTES (SMEM_WORDS * 4)

__global__ __launch_bounds__(NTHREADS, 3)
void snn_kernel(const float* __restrict__ x,
                const float* __restrict__ w1, const float* __restrict__ b1,
                const float* __restrict__ w2, const float* __restrict__ b2,
                const float* __restrict__ w3, const float* __restrict__ b3,
                const float* __restrict__ fb1,
                const float* __restrict__ fw2, const float* __restrict__ fb2,
                float* __restrict__ out)
{
    extern __shared__ float smem[];
    float* sw1p = smem + OFF_SW1P;
    float* sb1p = smem + OFF_SB1P;
    float* sw2p = smem + OFF_SW2P;
    float* sw3p = smem + OFF_SW3P;
    float* sx   = smem + OFF_SX;
    float* s1a  = smem + OFF_S1;
    float* s2a  = smem + OFF_S2;
    float* s4a  = smem + OFF_S4;
    unsigned* mska = (unsigned*)(smem + OFF_MSK);

    const int tid  = threadIdx.x;
    const int b    = blockIdx.x;
    const int lane = tid & 31;
    const int warp = tid >> 5;

    // ---- pack weights into smem ----
    for (int i = tid; i < C1 * K1; i += NTHREADS) {
        int co = i / K1, k = i - co * K1;
        sw1p[(k * 8 + (co >> 1)) * 2 + (co & 1)] = w1[i];
    }
    if (tid < C1) sb1p[tid] = b1[tid];
    for (int i = tid; i < C2 * C1 * K2; i += NTHREADS) {
        int co = i / (C1 * K2);
        int r = i - co * (C1 * K2);
        int ci = r / K2, k = r - ci * K2;
        sw2p[(((ci >> 1) * K2 + k) * C2 + co) * 2 + (ci & 1)] = w2[i];
    }
    for (int i = tid; i < C3 * C2 * K3; i += NTHREADS) {
        int co = i / (C2 * K3);
        int r = i - co * (C2 * K3);
        int ci = r / K3, k = r - ci * K3;
        sw3p[(((ci >> 1) * K3 + k) * C3 + co) * 2 + (ci & 1)] = w3[i];
    }
    // x -> smem transposed: sx[t*30+l]; global reads coalesced
    for (int i = tid; i < L0 * TSTEPS; i += NTHREADS) {
        int l = i / TSTEPS, tt = i - l * TSTEPS;
        sx[tt * L0 + l] = x[b * (L0 * TSTEPS) + i];
    }

    // ---- per-role register state ----
    // warp 0: conv1 (lanes 0-23, all 8 channel-pairs) + fc2 (lane 0 holds m5)
    u64 m1r[8];
    #pragma unroll
    for (int i = 0; i < 8; i++) m1r[i] = 0;
    float fb2r[NC], m5r[NC];
    #pragma unroll
    for (int i = 0; i < NC; i++) { fb2r[i] = 0.0f; m5r[i] = 0.0f; }
    if (warp == 0 && lane == 0)
        for (int j = 0; j < NC; j++) fb2r[j] = fb2[j];
    // warps 1-2: conv2, lane=co, l0=(warp-1)*10
    float b2r = 0.0f, m2r[10];
    #pragma unroll
    for (int i = 0; i < 10; i++) m2r[i] = 0.0f;
    if (warp == 1 || warp == 2) b2r = b2[lane];
    // warps 3-5: conv3, lane=co within half, l0=(warp-3)*6
    float b3r[2], m3r[2][6];
    b3r[0] = b3r[1] = 0.0f;
    #pragma unroll
    for (int h = 0; h < 2; h++)
        #pragma unroll
        for (int q = 0; q < 6; q++) m3r[h][q] = 0.0f;
    if (warp >= 3 && warp <= 5) { b3r[0] = b3[lane]; b3r[1] = b3[32 + lane]; }
    // warps 6-7: fc1, idx owns outputs 4idx..4idx+3
    const int fidx = (warp - 6) * 32 + lane;
    u64 fa0 = 0, fa1 = 0;  // bias template loaded below
    float m4r[4] = {0.0f, 0.0f, 0.0f, 0.0f};
    u64 fb1q0 = 0, fb1q1 = 0;
    if (warp >= 6) {
        fb1q0 = *(const u64*)(fb1 + 4 * fidx);
        fb1q1 = *(const u64*)(fb1 + 4 * fidx + 2);
    }
    (void)fa0; (void)fa1;
    __syncthreads();

    // ================= pipelined tick loop =================
    for (int tick = 0; tick < TSTEPS + 4; tick++) {
        if (warp == 0) {
            // ---- stage 1: conv1 at t1 = tick ----
            int t1 = tick;
            if (t1 < TSTEPS && lane < 24) {
                float* s1buf = s1a + (t1 & 1) * S1SZ;
                const float* xr = sx + t1 * L0 + lane;
                float xq[K1];
                #pragma unroll
                for (int k = 0; k < K1; k++) xq[k] = xr[k];
                #pragma unroll
                for (int cp = 0; cp < 8; cp++) {
                    u64 acc = lds64(sb1p + 2 * cp);
                    #pragma unroll
                    for (int k = 0; k < K1; k++)
                        acc = ffma2(lds64(sw1p + (k * 8 + cp) * 2), pack2(xq[k], xq[k]), acc);
                    float he, ho, me, mo;
                    unpack2(acc, he, ho);
                    unpack2(m1r[cp], me, mo);
                    float mne = lif_new_mem(me, he);
                    float mno = lif_new_mem(mo, ho);
                    m1r[cp] = pack2(mne, mno);
                    *(u64*)(s1buf + lane * S1W + 2 * cp) =
                        pack2((mne > 1.0f) ? 1.0f : 0.0f, (mno > 1.0f) ? 1.0f : 0.0f);
                }
            }
            // ---- stage 5: fc2 at t5 = tick-4 ----
            int t5 = tick - 4;
            if (t5 >= 0) {
                const float* s4buf = s4a + (t5 & 1) * S4SZ;
                #pragma unroll
                for (int j = 0; j < NC; j++) {
                    float acc = 0.0f;
                    #pragma unroll
                    for (int q = 0; q < 8; q++) {
                        int ii = lane + 32 * q;
                        acc = fmaf(__ldg(&fw2[j * H1 + ii]), s4buf[ii], acc);
                    }
                    #pragma unroll
                    for (int o = 16; o > 0; o >>= 1)
                        acc += __shfl_down_sync(0xffffffff, acc, o);
                    if (lane == 0) {
                        acc += fb2r[j];
                        float mn = lif_new_mem(m5r[j], acc);
                        m5r[j] = mn;
                        out[(t5 * BATCH + b) * NC + j] = (mn > 1.0f) ? 1.0f : 0.0f;
                    }
                }
            }
        } else if (warp <= 2) {
            // ---- stage 2: conv2 at t2 = tick-1; lane=co, 10 l each ----
            int t2 = tick - 1;
            if (t2 >= 0 && t2 < TSTEPS) {
                const float* s1buf = s1a + (t2 & 1) * S1SZ;
                float* s2buf = s2a + (t2 & 1) * S2SZ;
                const int co = lane;
                const int l0 = (warp - 1) * 10;
                u64 acc[10];
                u64 binit = pack2(b2r, 0.0f);
                #pragma unroll
                for (int q = 0; q < 10; q++) acc[q] = binit;
                #pragma unroll 2
                for (int p = 0; p < 8; p++) {
                    u64 w[K2];
                    #pragma unroll
                    for (int k = 0; k < K2; k++)
                        w[k] = lds64(sw2p + ((p * K2 + k) * C2 + co) * 2);
                    const float* sp = s1buf + l0 * S1W + 2 * p;
                    #pragma unroll
                    for (int d = 0; d < 14; d++) {
                        u64 sv = lds64(sp + d * S1W);
                        #pragma unroll
                        for (int k = 0; k < K2; k++) {
                            int q = d - k;
                            if (q >= 0 && q < 10) acc[q] = ffma2(w[k], sv, acc[q]);
                        }
                    }
                }
                #pragma unroll
                for (int q = 0; q < 10; q++) {
                    float lo, hi; unpack2(acc[q], lo, hi);
                    float h = __fadd_rn(lo, hi);
                    float mn = lif_new_mem(m2r[q], h);
                    m2r[q] = mn;
                    s2buf[(l0 + q) * C2 + co] = (mn > 1.0f) ? 1.0f : 0.0f;
                }
            }
        } else if (warp <= 5) {
            // ---- stage 3: conv3 at t3 = tick-2; lane=co in each half, 6 l each ----
            int t3 = tick - 2;
            if (t3 >= 0 && t3 < TSTEPS) {
                const float* s2buf = s2a + (t3 & 1) * S2SZ;
                unsigned* mkbuf = mska + (t3 & 1) * MSKSZ;
                const int T = warp - 3;
                const int l0 = T * 6;
                u64 acc[2][6];
                #pragma unroll
                for (int h = 0; h < 2; h++) {
                    u64 binit = pack2(b3r[h], 0.0f);
                    #pragma unroll
                    for (int q = 0; q < 6; q++) acc[h][q] = binit;
                }
                #pragma unroll 4
                for (int p = 0; p < 16; p++) {
                    u64 w[2][K3];
                    #pragma unroll
                    for (int h = 0; h < 2; h++)
                        #pragma unroll
                        for (int k = 0; k < K3; k++)
                            w[h][k] = lds64(sw3p + ((p * K3 + k) * C3 + h * 32 + lane) * 2);
                    const float* sp = s2buf + l0 * C2 + 2 * p;
                    #pragma unroll
                    for (int d = 0; d < 8; d++) {
                        u64 sv = lds64(sp + d * C2);
                        #pragma unroll
                        for (int h = 0; h < 2; h++)
                            #pragma unroll
                            for (int k = 0; k < K3; k++) {
                                int q = d - k;
                                if (q >= 0 && q < 6) acc[h][q] = ffma2(w[h][k], sv, acc[h][q]);
                            }
                    }
                }
                #pragma unroll
                for (int h = 0; h < 2; h++) {
                    unsigned bits = 0;
                    #pragma unroll
                    for (int q = 0; q < 6; q++) {
                        float lo, hi; unpack2(acc[h][q], lo, hi);
                        float hh = __fadd_rn(lo, hi);
                        float mn = lif_new_mem(m3r[h][q], hh);
                        m3r[h][q] = mn;
                        if (mn > 1.0f) bits |= 1u << q;
                    }
                    mkbuf[T * 64 + h * 32 + lane] = bits;   // exclusive store, no atomics
                }
            }
        } else {
            // ---- stage 4: fc1 at t4 = tick-3; 64 threads, 4 outputs each ----
            int t4 = tick - 3;
            if (t4 >= 0 && t4 < TSTEPS) {
                const unsigned* mk = mska + (t4 & 1) * MSKSZ;
                float* s4buf = s4a + (t4 & 1) * S4SZ;
                u64 a0 = fb1q0, a1 = fb1q1;
                #pragma unroll 4
                for (int r = 0; r < C3; r++) {
                    unsigned m = mk[r] | (mk[64 + r] << 6) | (mk[128 + r] << 12);
                    const char* base = (const char*)(g_fw1T + r * (L3 * H1) + 4 * fidx);
                    while (m) {
                        int l = __ffs(m) - 1;
                        m &= m - 1;
                        ulonglong2 v = *(const ulonglong2*)(base + l * (H1 * 4));
                        a0 = fadd2(a0, v.x);
                        a1 = fadd2(a1, v.y);
                    }
                }
                float f0, f1, f2, f3;
                unpack2(a0, f0, f1);
                unpack2(a1, f2, f3);
                float mn0 = lif_new_mem(m4r[0], f0);
                float mn1 = lif_new_mem(m4r[1], f1);
                float mn2 = lif_new_mem(m4r[2], f2);
                float mn3 = lif_new_mem(m4r[3], f3);
                m4r[0] = mn0; m4r[1] = mn1; m4r[2] = mn2; m4r[3] = mn3;
                float4 sp;
                sp.x = (mn0 > 1.0f) ? 1.0f : 0.0f;
                sp.y = (mn1 > 1.0f) ? 1.0f : 0.0f;
                sp.z = (mn2 > 1.0f) ? 1.0f : 0.0f;
                sp.w = (mn3 > 1.0f) ? 1.0f : 0.0f;
                *(float4*)(s4buf + 4 * fidx) = sp;
            }
        }
        __syncthreads();   // single pipeline tick barrier
    }
}

extern "C" void kernel_launch(void* const* d_in, const int* in_sizes, int n_in,
                              void* d_out, int out_size) {
    const float* x   = (const float*)d_in[0];
    const float* w1  = (const float*)d_in[1];
    const float* b1  = (const float*)d_in[2];
    const float* w2  = (const float*)d_in[3];
    const float* b2  = (const float*)d_in[4];
    const float* w3  = (const float*)d_in[5];
    const float* b3  = (const float*)d_in[6];
    const float* fw1 = (const float*)d_in[7];
    const float* fb1 = (const float*)d_in[8];
    const float* fw2 = (const float*)d_in[9];
    const float* fb2 = (const float*)d_in[10];
    float* out = (float*)d_out;

    cudaFuncSetAttribute(snn_kernel, cudaFuncAttributeMaxDynamicSharedMemorySize, SMEM_BYTES);

    transpose_fw1_kernel<<<(H1 * F1 + 255) / 256, 256>>>(fw1);
    snn_kernel<<<BATCH, NTHREADS, SMEM_BYTES>>>(x, w1, b1, w2, b2, w3, b3,
                                                fb1, fw2, fb2, out);
}

// round 6
// speedup vs baseline: 1.3208x; 1.1632x over previous
#include <cuda_runtime.h>

#define BATCH   1024
#define TSTEPS  100
#define L0      30
#define C1      16
#define L1      24
#define K1      7
#define C2      32
#define L2      20
#define K2      5
#define C3      64
#define L3      18
#define K3      3
#define F1      1152   // 64*18
#define H1      256
#define NC      10

#define NTHREADS 256

typedef unsigned long long u64;

// Transposed fc1 weights: fw1T[i*H1 + j] = fw1[j*F1 + i]
__device__ __align__(16) float g_fw1T[F1 * H1];

__global__ void transpose_fw1_kernel(const float* __restrict__ fw1) {
    int idx = blockIdx.x * blockDim.x + threadIdx.x;
    if (idx < H1 * F1) {
        int j = idx / F1;
        int i = idx - j * F1;
        g_fw1T[i * H1 + j] = fw1[idx];
    }
}

// ---- f32x2 helpers ----
__device__ __forceinline__ u64 ffma2(u64 a, u64 b, u64 c) {
    u64 d; asm("fma.rn.f32x2 %0, %1, %2, %3;" : "=l"(d) : "l"(a), "l"(b), "l"(c)); return d;
}
__device__ __forceinline__ u64 fadd2(u64 a, u64 b) {
    u64 d; asm("add.rn.f32x2 %0, %1, %2;" : "=l"(d) : "l"(a), "l"(b)); return d;
}
__device__ __forceinline__ u64 pack2(float lo, float hi) {
    u64 r; asm("mov.b64 %0, {%1, %2};" : "=l"(r) : "f"(lo), "f"(hi)); return r;
}
__device__ __forceinline__ void unpack2(u64 v, float& lo, float& hi) {
    asm("mov.b64 {%0, %1}, %2;" : "=f"(lo), "=f"(hi) : "l"(v));
}
__device__ __forceinline__ u64 lds64(const float* p) { return *(const u64*)p; }

// LIF: reset from PREVIOUS mem (subtract), spike on new mem.
// No FMA contraction: match reference op sequence 0.9*m + h - reset.
__device__ __forceinline__ float lif_new_mem(float m_old, float h) {
    float reset = (m_old > 1.0f) ? 1.0f : 0.0f;
    return __fadd_rn(__fadd_rn(__fmul_rn(0.9f, m_old), h), -reset);
}

// smem layout (words)
#define OFF_SW1T 0        // 112: [k*16+co]
#define OFF_SB1  112      // 16
#define OFF_SW2P 128      // 2560: [((p*5+k)*32+co)*2+e]
#define OFF_SW3P 2688     // 6144: [((p*3+k)*64+co)*2+e]
#define OFF_SX   8832     // 2*3000: [half][t*30+l]
#define OFF_S1   14832    // 2*384:  [half][l*16+co]
#define OFF_S2   15600    // 2*640:  [half][l*32+co]
#define OFF_S4   16880    // 2*256:  [half][j]
#define OFF_MSK  17392    // 2*128:  [half][T*64+co]
#define SMEM_WORDS 17648
#define SMEM_BYTES (SMEM_WORDS * 4)

__global__ __launch_bounds__(NTHREADS, 2)
void snn_kernel(const float* __restrict__ x,
                const float* __restrict__ w1, const float* __restrict__ b1,
                const float* __restrict__ w2, const float* __restrict__ b2,
                const float* __restrict__ w3, const float* __restrict__ b3,
                const float* __restrict__ fb1,
                const float* __restrict__ fw2, const float* __restrict__ fb2,
                float* __restrict__ out)
{
    extern __shared__ float smem[];
    float* sw1t = smem + OFF_SW1T;
    float* sb1  = smem + OFF_SB1;
    float* sw2p = smem + OFF_SW2P;
    float* sw3p = smem + OFF_SW3P;

    const int tid  = threadIdx.x;
    const int lane = tid & 31;
    const int warp = tid >> 5;
    const int half = warp >> 2;          // 0: warps 0-3 (sample A), 1: warps 4-7 (sample B)
    const int hwarp = warp & 3;
    const int htid = (hwarp << 5) | lane;  // 0..127 within half
    const int b = 2 * blockIdx.x + half;   // this half's batch sample

    float* sx    = smem + OFF_SX  + half * 3000;   // [t*30 + l]
    float* s1buf = smem + OFF_S1  + half * 384;    // [l*16 + co]
    float* s2buf = smem + OFF_S2  + half * 640;    // [l*32 + co]
    float* s4buf = smem + OFF_S4  + half * 256;
    unsigned* mkbuf = (unsigned*)(smem + OFF_MSK) + half * 128;

    // ---- pack weights into smem (all 256 threads) ----
    for (int i = tid; i < C1 * K1; i += NTHREADS) {
        int co = i / K1, k = i - co * K1;
        sw1t[k * C1 + co] = w1[i];
    }
    if (tid < C1) sb1[tid] = b1[tid];
    for (int i = tid; i < C2 * C1 * K2; i += NTHREADS) {
        int co = i / (C1 * K2);
        int r = i - co * (C1 * K2);
        int ci = r / K2, k = r - ci * K2;
        sw2p[(((ci >> 1) * K2 + k) * C2 + co) * 2 + (ci & 1)] = w2[i];
    }
    for (int i = tid; i < C3 * C2 * K3; i += NTHREADS) {
        int co = i / (C2 * K3);
        int r = i - co * (C2 * K3);
        int ci = r / K3, k = r - ci * K3;
        sw3p[(((ci >> 1) * K3 + k) * C3 + co) * 2 + (ci & 1)] = w3[i];
    }
    // x -> smem transposed per sample: sx[t*30+l] (coalesced gmem reads)
    for (int i = tid; i < 2 * L0 * TSTEPS; i += NTHREADS) {
        int h = i / 3000, r = i - h * 3000;
        int l = r / TSTEPS, tt = r - l * TSTEPS;
        smem[OFF_SX + h * 3000 + tt * L0 + l] = x[(2 * blockIdx.x + h) * 3000 + r];
    }

    // ---- per-thread register state ----
    float m1r[3] = {0.0f, 0.0f, 0.0f};
    const float b2r = b2[lane];
    float m2r[5] = {0.0f, 0.0f, 0.0f, 0.0f, 0.0f};
    const int l02 = hwarp * 5;
    const int co3 = ((hwarp & 1) << 5) | lane;
    const int T3  = hwarp >> 1;
    const int l03 = T3 * 9;
    const float b3r = b3[co3];
    float m3r[9];
    #pragma unroll
    for (int q = 0; q < 9; q++) m3r[q] = 0.0f;
    const u64 fb1p = *(const u64*)(fb1 + 2 * htid);
    float m4a = 0.0f, m4b = 0.0f;
    float fb2r[3] = {0.0f, 0.0f, 0.0f}, m5r[3] = {0.0f, 0.0f, 0.0f};
    if (lane == 0) {
        #pragma unroll
        for (int i = 0; i < 3; i++) {
            int j = hwarp + 4 * i;
            if (j < NC) fb2r[i] = fb2[j];
        }
    }
    __syncthreads();

    for (int t = 0; t < TSTEPS; t++) {
        // ======== conv1 (1->16, k=7): 128 threads/sample, 3 outputs each ========
        {
            const float* xr = sx + t * L0;
            #pragma unroll
            for (int it = 0; it < 3; it++) {
                int idx = htid + it * 128;
                int l = idx >> 4, co = idx & 15;
                float acc = sb1[co];
                #pragma unroll
                for (int k = 0; k < K1; k++)
                    acc = fmaf(sw1t[k * C1 + co], xr[l + k], acc);
                float mn = lif_new_mem(m1r[it], acc);
                m1r[it] = mn;
                s1buf[idx] = (mn > 1.0f) ? 1.0f : 0.0f;
            }
        }
        __syncthreads();   // S1

        // ======== conv2 (16->32, k=5): co=lane, 5 l per thread ========
        {
            u64 acc[5];
            u64 binit = pack2(b2r, 0.0f);
            #pragma unroll
            for (int q = 0; q < 5; q++) acc[q] = binit;
            #pragma unroll 2
            for (int p = 0; p < 8; p++) {
                u64 w[K2];
                #pragma unroll
                for (int k = 0; k < K2; k++)
                    w[k] = lds64(sw2p + ((p * K2 + k) * C2 + lane) * 2);
                const float* sp = s1buf + l02 * C1 + 2 * p;
                #pragma unroll
                for (int d = 0; d < 9; d++) {
                    u64 sv = lds64(sp + d * C1);
                    #pragma unroll
                    for (int k = 0; k < K2; k++) {
                        int q = d - k;
                        if (q >= 0 && q < 5) acc[q] = ffma2(w[k], sv, acc[q]);
                    }
                }
            }
            #pragma unroll
            for (int q = 0; q < 5; q++) {
                float lo, hi; unpack2(acc[q], lo, hi);
                float h = __fadd_rn(lo, hi);
                float mn = lif_new_mem(m2r[q], h);
                m2r[q] = mn;
                s2buf[(l02 + q) * C2 + lane] = (mn > 1.0f) ? 1.0f : 0.0f;
            }
        }
        __syncthreads();   // S2

        // ======== conv3 (32->64, k=3): co3, 9 l per thread ========
        {
            u64 acc[9];
            u64 binit = pack2(b3r, 0.0f);
            #pragma unroll
            for (int q = 0; q < 9; q++) acc[q] = binit;
            #pragma unroll 4
            for (int p = 0; p < 16; p++) {
                u64 w[K3];
                #pragma unroll
                for (int k = 0; k < K3; k++)
                    w[k] = lds64(sw3p + ((p * K3 + k) * C3 + co3) * 2);
                const float* sp = s2buf + l03 * C2 + 2 * p;
                #pragma unroll
                for (int d = 0; d < 11; d++) {
                    u64 sv = lds64(sp + d * C2);
                    #pragma unroll
                    for (int k = 0; k < K3; k++) {
                        int q = d - k;
                        if (q >= 0 && q < 9) acc[q] = ffma2(w[k], sv, acc[q]);
                    }
                }
            }
            unsigned bits = 0;
            #pragma unroll
            for (int q = 0; q < 9; q++) {
                float lo, hi; unpack2(acc[q], lo, hi);
                float h = __fadd_rn(lo, hi);
                float mn = lif_new_mem(m3r[q], h);
                m3r[q] = mn;
                if (mn > 1.0f) bits |= 1u << q;
            }
            mkbuf[T3 * 64 + co3] = bits;   // exclusive store, no atomics
        }
        __syncthreads();   // S3

        // ======== fc1 (1152->256): all 128 threads/sample, 2 outputs each ========
        {
            u64 acc = fb1p;
            #pragma unroll 4
            for (int r = 0; r < C3; r++) {
                unsigned m = mkbuf[r] | (mkbuf[64 + r] << 9);   // 18 bits, l ascending
                const float* base = g_fw1T + r * (L3 * H1) + 2 * htid;
                while (m) {
                    int l = __ffs(m) - 1;
                    m &= m - 1;
                    acc = fadd2(acc, __ldg((const u64*)(base + l * H1)));
                }
            }
            float lo, hi; unpack2(acc, lo, hi);
            float mn0 = lif_new_mem(m4a, lo);
            float mn1 = lif_new_mem(m4b, hi);
            m4a = mn0; m4b = mn1;
            *(u64*)(s4buf + 2 * htid) =
                pack2((mn0 > 1.0f) ? 1.0f : 0.0f, (mn1 > 1.0f) ? 1.0f : 0.0f);
        }
        __syncthreads();   // S4

        // ======== fc2 (256->10) + output ========
        {
            #pragma unroll
            for (int i = 0; i < 3; i++) {
                int j = hwarp + 4 * i;
                if (j < NC) {
                    float acc = 0.0f;
                    #pragma unroll
                    for (int q = 0; q < 8; q++) {
                        int ii = lane + 32 * q;
                        acc = fmaf(__ldg(&fw2[j * H1 + ii]), s4buf[ii], acc);
                    }
                    #pragma unroll
                    for (int o = 16; o > 0; o >>= 1)
                        acc += __shfl_down_sync(0xffffffff, acc, o);
                    if (lane == 0) {
                        acc += fb2r[i];
                        float mn = lif_new_mem(m5r[i], acc);
                        m5r[i] = mn;
                        out[(t * BATCH + b) * NC + j] = (mn > 1.0f) ? 1.0f : 0.0f;
                    }
                }
            }
        }
        // no trailing sync: fc2 reads s4/fw2 only; next conv1 writes s1,
        // whose next readers (conv2) are separated by S1; s4's next writer
        // (fc1) is three barriers away.
    }
}

extern "C" void kernel_launch(void* const* d_in, const int* in_sizes, int n_in,
                              void* d_out, int out_size) {
    const float* x   = (const float*)d_in[0];
    const float* w1  = (const float*)d_in[1];
    const float* b1  = (const float*)d_in[2];
    const float* w2  = (const float*)d_in[3];
    const float* b2  = (const float*)d_in[4];
    const float* w3  = (const float*)d_in[5];
    const float* b3  = (const float*)d_in[6];
    const float* fw1 = (const float*)d_in[7];
    const float* fb1 = (const float*)d_in[8];
    const float* fw2 = (const float*)d_in[9];
    const float* fb2 = (const float*)d_in[10];
    float* out = (float*)d_out;

    cudaFuncSetAttribute(snn_kernel, cudaFuncAttributeMaxDynamicSharedMemorySize, SMEM_BYTES);

    transpose_fw1_kernel<<<(H1 * F1 + 255) / 256, 256>>>(fw1);
    snn_kernel<<<BATCH / 2, NTHREADS, SMEM_BYTES>>>(x, w1, b1, w2, b2, w3, b3,
                                                    fb1, fw2, fb2, out);
}

// round 7
// speedup vs baseline: 1.4793x; 1.1200x over previous
#include <cuda_runtime.h>

#define BATCH   1024
#define TSTEPS  100
#define L0      30
#define C1      16
#define L1      24
#define K1      7
#define C2      32
#define L2      20
#define K2      5
#define C3      64
#define L3      18
#define K3      3
#define F1      1152   // 64*18
#define H1      256
#define NC      10

#define NTHREADS 256

typedef unsigned long long u64;

// Transposed fc1 weights: fw1T[i*H1 + j] = fw1[j*F1 + i]
__device__ __align__(16) float g_fw1T[F1 * H1];

__global__ void transpose_fw1_kernel(const float* __restrict__ fw1) {
    int idx = blockIdx.x * blockDim.x + threadIdx.x;
    if (idx < H1 * F1) {
        int j = idx / F1;
        int i = idx - j * F1;
        g_fw1T[i * H1 + j] = fw1[idx];
    }
}

// ---- f32x2 helpers ----
__device__ __forceinline__ u64 ffma2(u64 a, u64 b, u64 c) {
    u64 d; asm("fma.rn.f32x2 %0, %1, %2, %3;" : "=l"(d) : "l"(a), "l"(b), "l"(c)); return d;
}
__device__ __forceinline__ u64 fadd2(u64 a, u64 b) {
    u64 d; asm("add.rn.f32x2 %0, %1, %2;" : "=l"(d) : "l"(a), "l"(b)); return d;
}
__device__ __forceinline__ u64 pack2(float lo, float hi) {
    u64 r; asm("mov.b64 %0, {%1, %2};" : "=l"(r) : "f"(lo), "f"(hi)); return r;
}
__device__ __forceinline__ void unpack2(u64 v, float& lo, float& hi) {
    asm("mov.b64 {%0, %1}, %2;" : "=f"(lo), "=f"(hi) : "l"(v));
}
__device__ __forceinline__ u64 lds64(const float* p) { return *(const u64*)p; }

// LIF: reset from PREVIOUS mem (subtract), spike on new mem.
// No FMA contraction: match reference op sequence 0.9*m + h - reset.
__device__ __forceinline__ float lif_new_mem(float m_old, float h) {
    float reset = (m_old > 1.0f) ? 1.0f : 0.0f;
    return __fadd_rn(__fadd_rn(__fmul_rn(0.9f, m_old), h), -reset);
}

// smem layout (words)
#define OFF_SW1T 0        // 112: [k*16+co]
#define OFF_SB1  112      // 16
#define OFF_SW2P 128      // 2560: [((p*5+k)*32+co)*2+e]
#define OFF_SW3P 2688     // 6144: [((p*3+k)*64+co)*2+e]
#define OFF_XB   8832     // 2*2*32 = 128: [half][buf][l]
#define OFF_S1   8960     // 2*384:  [half][l*16+co]
#define OFF_S2   9728     // 2*640:  [half][l*32+co]
#define OFF_S4   11008    // 2*256:  [half][j]
#define OFF_MSK  11520    // 2*128:  [half][T*64+co]
#define SMEM_WORDS 11776
#define SMEM_BYTES (SMEM_WORDS * 4)

__global__ __launch_bounds__(NTHREADS, 4)
void snn_kernel(const float* __restrict__ x,
                const float* __restrict__ w1, const float* __restrict__ b1,
                const float* __restrict__ w2, const float* __restrict__ b2,
                const float* __restrict__ w3, const float* __restrict__ b3,
                const float* __restrict__ fb1,
                const float* __restrict__ fw2, const float* __restrict__ fb2,
                float* __restrict__ out)
{
    extern __shared__ float smem[];
    float* sw1t = smem + OFF_SW1T;
    float* sb1  = smem + OFF_SB1;
    float* sw2p = smem + OFF_SW2P;
    float* sw3p = smem + OFF_SW3P;

    const int tid  = threadIdx.x;
    const int lane = tid & 31;
    const int warp = tid >> 5;
    const int half = warp >> 2;            // 0: warps 0-3 (sample A), 1: warps 4-7 (sample B)
    const int hwarp = warp & 3;
    const int htid = (hwarp << 5) | lane;  // 0..127 within half
    const int b = 2 * blockIdx.x + half;   // this half's batch sample

    float* xb    = smem + OFF_XB  + half * 64;     // [buf*32 + l]
    float* s1buf = smem + OFF_S1  + half * 384;    // [l*16 + co]
    float* s2buf = smem + OFF_S2  + half * 640;    // [l*32 + co]
    float* s4buf = smem + OFF_S4  + half * 256;
    unsigned* mkbuf = (unsigned*)(smem + OFF_MSK) + half * 128;

    // ---- pack weights into smem (all 256 threads) ----
    for (int i = tid; i < C1 * K1; i += NTHREADS) {
        int co = i / K1, k = i - co * K1;
        sw1t[k * C1 + co] = w1[i];
    }
    if (tid < C1) sb1[tid] = b1[tid];
    for (int i = tid; i < C2 * C1 * K2; i += NTHREADS) {
        int co = i / (C1 * K2);
        int r = i - co * (C1 * K2);
        int ci = r / K2, k = r - ci * K2;
        sw2p[(((ci >> 1) * K2 + k) * C2 + co) * 2 + (ci & 1)] = w2[i];
    }
    for (int i = tid; i < C3 * C2 * K3; i += NTHREADS) {
        int co = i / (C2 * K3);
        int r = i - co * (C2 * K3);
        int ci = r / K3, k = r - ci * K3;
        sw3p[(((ci >> 1) * K3 + k) * C3 + co) * 2 + (ci & 1)] = w3[i];
    }
    // x prefetch for t=0: x[b,0,l,0] at stride TSTEPS
    if (hwarp == 0 && lane < L0)
        xb[lane] = __ldg(&x[b * (L0 * TSTEPS) + lane * TSTEPS]);

    // ---- per-thread register state ----
    float m1r[3] = {0.0f, 0.0f, 0.0f};
    const float b2r = b2[lane];
    float m2r[5] = {0.0f, 0.0f, 0.0f, 0.0f, 0.0f};
    const int l02 = hwarp * 5;
    const int co3 = ((hwarp & 1) << 5) | lane;
    const int T3  = hwarp >> 1;
    const int l03 = T3 * 9;
    const float b3r = b3[co3];
    float m3r[9];
    #pragma unroll
    for (int q = 0; q < 9; q++) m3r[q] = 0.0f;
    float m4a = 0.0f, m4b = 0.0f;
    float m5r[3] = {0.0f, 0.0f, 0.0f};
    __syncthreads();

    for (int t = 0; t < TSTEPS; t++) {
        // ======== conv1 (1->16, k=7): 128 threads/sample, 3 outputs each ========
        {
            const float* xr = xb + (t & 1) * 32;
            // prefetch x for t+1 into the other buffer (visible after S1..S4)
            if (hwarp == 0 && lane < L0 && t + 1 < TSTEPS)
                xb[((t + 1) & 1) * 32 + lane] =
                    __ldg(&x[b * (L0 * TSTEPS) + lane * TSTEPS + t + 1]);
            #pragma unroll
            for (int it = 0; it < 3; it++) {
                int idx = htid + it * 128;
                int l = idx >> 4, co = idx & 15;
                float acc = sb1[co];
                #pragma unroll
                for (int k = 0; k < K1; k++)
                    acc = fmaf(sw1t[k * C1 + co], xr[l + k], acc);
                float mn = lif_new_mem(m1r[it], acc);
                m1r[it] = mn;
                s1buf[idx] = (mn > 1.0f) ? 1.0f : 0.0f;
            }
        }
        __syncthreads();   // S1

        // ======== conv2 (16->32, k=5): co=lane, 5 l per thread ========
        {
            u64 acc[5];
            u64 binit = pack2(b2r, 0.0f);
            #pragma unroll
            for (int q = 0; q < 5; q++) acc[q] = binit;
            #pragma unroll 2
            for (int p = 0; p < 8; p++) {
                u64 w[K2];
                #pragma unroll
                for (int k = 0; k < K2; k++)
                    w[k] = lds64(sw2p + ((p * K2 + k) * C2 + lane) * 2);
                const float* sp = s1buf + l02 * C1 + 2 * p;
                #pragma unroll
                for (int d = 0; d < 9; d++) {
                    u64 sv = lds64(sp + d * C1);
                    #pragma unroll
                    for (int k = 0; k < K2; k++) {
                        int q = d - k;
                        if (q >= 0 && q < 5) acc[q] = ffma2(w[k], sv, acc[q]);
                    }
                }
            }
            #pragma unroll
            for (int q = 0; q < 5; q++) {
                float lo, hi; unpack2(acc[q], lo, hi);
                float h = __fadd_rn(lo, hi);
                float mn = lif_new_mem(m2r[q], h);
                m2r[q] = mn;
                s2buf[(l02 + q) * C2 + lane] = (mn > 1.0f) ? 1.0f : 0.0f;
            }
        }
        __syncthreads();   // S2

        // ======== conv3 (32->64, k=3): co3, 9 l per thread ========
        {
            u64 acc[9];
            u64 binit = pack2(b3r, 0.0f);
            #pragma unroll
            for (int q = 0; q < 9; q++) acc[q] = binit;
            #pragma unroll 4
            for (int p = 0; p < 16; p++) {
                u64 w[K3];
                #pragma unroll
                for (int k = 0; k < K3; k++)
                    w[k] = lds64(sw3p + ((p * K3 + k) * C3 + co3) * 2);
                const float* sp = s2buf + l03 * C2 + 2 * p;
                #pragma unroll
                for (int d = 0; d < 11; d++) {
                    u64 sv = lds64(sp + d * C2);
                    #pragma unroll
                    for (int k = 0; k < K3; k++) {
                        int q = d - k;
                        if (q >= 0 && q < 9) acc[q] = ffma2(w[k], sv, acc[q]);
                    }
                }
            }
            unsigned bits = 0;
            #pragma unroll
            for (int q = 0; q < 9; q++) {
                float lo, hi; unpack2(acc[q], lo, hi);
                float h = __fadd_rn(lo, hi);
                float mn = lif_new_mem(m3r[q], h);
                m3r[q] = mn;
                if (mn > 1.0f) bits |= 1u << q;
            }
            mkbuf[T3 * 64 + co3] = bits;   // exclusive store, no atomics
        }
        __syncthreads();   // S3

        // ======== fc1 (1152->256): all 128 threads/sample, 2 outputs each ========
        {
            u64 acc = __ldg((const u64*)(fb1 + 2 * htid));
            #pragma unroll 4
            for (int r = 0; r < C3; r++) {
                unsigned m = mkbuf[r] | (mkbuf[64 + r] << 9);   // 18 bits, l ascending
                const float* base = g_fw1T + r * (L3 * H1) + 2 * htid;
                while (m) {
                    int l = __ffs(m) - 1;
                    m &= m - 1;
                    acc = fadd2(acc, __ldg((const u64*)(base + l * H1)));
                }
            }
            float lo, hi; unpack2(acc, lo, hi);
            float mn0 = lif_new_mem(m4a, lo);
            float mn1 = lif_new_mem(m4b, hi);
            m4a = mn0; m4b = mn1;
            *(u64*)(s4buf + 2 * htid) =
                pack2((mn0 > 1.0f) ? 1.0f : 0.0f, (mn1 > 1.0f) ? 1.0f : 0.0f);
        }
        __syncthreads();   // S4

        // ======== fc2 (256->10) + output ========
        {
            #pragma unroll
            for (int i = 0; i < 3; i++) {
                int j = hwarp + 4 * i;
                if (j < NC) {
                    float acc = 0.0f;
                    #pragma unroll
                    for (int q = 0; q < 8; q++) {
                        int ii = lane + 32 * q;
                        acc = fmaf(__ldg(&fw2[j * H1 + ii]), s4buf[ii], acc);
                    }
                    #pragma unroll
                    for (int o = 16; o > 0; o >>= 1)
                        acc += __shfl_down_sync(0xffffffff, acc, o);
                    if (lane == 0) {
                        acc += __ldg(&fb2[j]);
                        float mn = lif_new_mem(m5r[i], acc);
                        m5r[i] = mn;
                        out[(t * BATCH + b) * NC + j] = (mn > 1.0f) ? 1.0f : 0.0f;
                    }
                }
            }
        }
        // no trailing sync: fc2 reads s4/fw2 only; next conv1 writes s1/xb(other buf),
        // whose next readers are separated by S1.
    }
}

extern "C" void kernel_launch(void* const* d_in, const int* in_sizes, int n_in,
                              void* d_out, int out_size) {
    const float* x   = (const float*)d_in[0];
    const float* w1  = (const float*)d_in[1];
    const float* b1  = (const float*)d_in[2];
    const float* w2  = (const float*)d_in[3];
    const float* b2  = (const float*)d_in[4];
    const float* w3  = (const float*)d_in[5];
    const float* b3  = (const float*)d_in[6];
    const float* fw1 = (const float*)d_in[7];
    const float* fb1 = (const float*)d_in[8];
    const float* fw2 = (const float*)d_in[9];
    const float* fb2 = (const float*)d_in[10];
    float* out = (float*)d_out;

    cudaFuncSetAttribute(snn_kernel, cudaFuncAttributeMaxDynamicSharedMemorySize, SMEM_BYTES);

    transpose_fw1_kernel<<<(H1 * F1 + 255) / 256, 256>>>(fw1);
    snn_kernel<<<BATCH / 2, NTHREADS, SMEM_BYTES>>>(x, w1, b1, w2, b2, w3, b3,
                                                    fb1, fw2, fb2, out);
}

// round 8
// speedup vs baseline: 1.7808x; 1.2038x over previous
#include <cuda_runtime.h>

#define BATCH   1024
#define TSTEPS  100
#define L0      30
#define C1      16
#define L1      24
#define K1      7
#define C2      32
#define L2      20
#define K2      5
#define C3      64
#define L3      18
#define K3      3
#define F1      1152   // 64*18
#define H1      256
#define NC      10

#define NTHREADS 256

typedef unsigned long long u64;

// Transposed fc1 weights: fw1T[i*H1 + j] = fw1[j*F1 + i]
__device__ __align__(16) float g_fw1T[F1 * H1];

__global__ void transpose_fw1_kernel(const float* __restrict__ fw1) {
    int idx = blockIdx.x * blockDim.x + threadIdx.x;
    if (idx < H1 * F1) {
        int j = idx / F1;
        int i = idx - j * F1;
        g_fw1T[i * H1 + j] = fw1[idx];
    }
}

// ---- f32x2 helpers ----
__device__ __forceinline__ u64 ffma2(u64 a, u64 b, u64 c) {
    u64 d; asm("fma.rn.f32x2 %0, %1, %2, %3;" : "=l"(d) : "l"(a), "l"(b), "l"(c)); return d;
}
__device__ __forceinline__ u64 fadd2(u64 a, u64 b) {
    u64 d; asm("add.rn.f32x2 %0, %1, %2;" : "=l"(d) : "l"(a), "l"(b)); return d;
}
__device__ __forceinline__ u64 pack2(float lo, float hi) {
    u64 r; asm("mov.b64 %0, {%1, %2};" : "=l"(r) : "f"(lo), "f"(hi)); return r;
}
__device__ __forceinline__ void unpack2(u64 v, float& lo, float& hi) {
    asm("mov.b64 {%0, %1}, %2;" : "=f"(lo), "=f"(hi) : "l"(v));
}
__device__ __forceinline__ u64 lds64(const float* p) { return *(const u64*)p; }

// half-scoped barrier: 128 threads, ids 1 (half 0) / 2 (half 1)
__device__ __forceinline__ void barh(int id) {
    asm volatile("bar.sync %0, 128;" :: "r"(id) : "memory");
}

// LIF: reset from PREVIOUS mem (subtract), spike on new mem.
// No FMA contraction: match reference op sequence 0.9*m + h - reset.
__device__ __forceinline__ float lif_new_mem(float m_old, float h) {
    float reset = (m_old > 1.0f) ? 1.0f : 0.0f;
    return __fadd_rn(__fadd_rn(__fmul_rn(0.9f, m_old), h), -reset);
}

// smem layout (words)
#define OFF_SW1T 0        // 112: [k*16+co]
#define OFF_SB1  112      // 16
#define OFF_SW2P 128      // 2560: [((p*5+k)*32+co)*2+e]
#define OFF_SW3P 2688     // 6144: [((p*3+k)*64+co)*2+e]
#define OFF_XB   8832     // 2*2*32 = 128: [half][buf][l]
#define OFF_S1   8960     // 2*384:  [half][l*16+co]
#define OFF_S2   9728     // 2*640:  [half][l*32+co]
#define OFF_S4   11008    // 2*256:  [half][j]
#define OFF_MSK  11520    // 2*128:  [half][T*64+co]
#define OFF_NACT 11776    // 2
#define OFF_ACT  11778    // 2*576 words = 2*1152 u16  (8B aligned: 11778*4 = 47112 ✓)
#define SMEM_WORDS 12930
#define SMEM_BYTES (SMEM_WORDS * 4)

__global__ __launch_bounds__(NTHREADS, 4)
void snn_kernel(const float* __restrict__ x,
                const float* __restrict__ w1, const float* __restrict__ b1,
                const float* __restrict__ w2, const float* __restrict__ b2,
                const float* __restrict__ w3, const float* __restrict__ b3,
                const float* __restrict__ fb1,
                const float* __restrict__ fw2, const float* __restrict__ fb2,
                float* __restrict__ out)
{
    extern __shared__ float smem[];
    float* sw1t = smem + OFF_SW1T;
    float* sb1  = smem + OFF_SB1;
    float* sw2p = smem + OFF_SW2P;
    float* sw3p = smem + OFF_SW3P;

    const int tid  = threadIdx.x;
    const int lane = tid & 31;
    const int warp = tid >> 5;
    const int half = warp >> 2;            // 0: warps 0-3 (sample A), 1: warps 4-7 (sample B)
    const int hwarp = warp & 3;
    const int htid = (hwarp << 5) | lane;  // 0..127 within half
    const int b = 2 * blockIdx.x + half;   // this half's batch sample
    const int barid = 1 + half;

    float* xb    = smem + OFF_XB  + half * 64;     // [buf*32 + l]
    float* s1buf = smem + OFF_S1  + half * 384;    // [l*16 + co]
    float* s2buf = smem + OFF_S2  + half * 640;    // [l*32 + co]
    float* s4buf = smem + OFF_S4  + half * 256;
    unsigned* mkbuf = (unsigned*)(smem + OFF_MSK) + half * 128;
    int* nact = (int*)(smem + OFF_NACT) + half;
    unsigned short* act = (unsigned short*)(smem + OFF_ACT) + half * 1152;

    // ---- pack weights into smem (all 256 threads) ----
    for (int i = tid; i < C1 * K1; i += NTHREADS) {
        int co = i / K1, k = i - co * K1;
        sw1t[k * C1 + co] = w1[i];
    }
    if (tid < C1) sb1[tid] = b1[tid];
    for (int i = tid; i < C2 * C1 * K2; i += NTHREADS) {
        int co = i / (C1 * K2);
        int r = i - co * (C1 * K2);
        int ci = r / K2, k = r - ci * K2;
        sw2p[(((ci >> 1) * K2 + k) * C2 + co) * 2 + (ci & 1)] = w2[i];
    }
    for (int i = tid; i < C3 * C2 * K3; i += NTHREADS) {
        int co = i / (C2 * K3);
        int r = i - co * (C2 * K3);
        int ci = r / K3, k = r - ci * K3;
        sw3p[(((ci >> 1) * K3 + k) * C3 + co) * 2 + (ci & 1)] = w3[i];
    }
    // x prefetch for t=0
    if (hwarp == 0 && lane < L0)
        xb[lane] = __ldg(&x[b * (L0 * TSTEPS) + lane * TSTEPS]);

    // ---- per-thread register state ----
    float m1r[3] = {0.0f, 0.0f, 0.0f};
    const float b2r = b2[lane];
    float m2r[5] = {0.0f, 0.0f, 0.0f, 0.0f, 0.0f};
    const int l02 = hwarp * 5;
    const int co3 = ((hwarp & 1) << 5) | lane;
    const int T3  = hwarp >> 1;
    const int l03 = T3 * 9;
    const float b3r = b3[co3];
    float m3r[9];
    #pragma unroll
    for (int q = 0; q < 9; q++) m3r[q] = 0.0f;
    float m4a = 0.0f, m4b = 0.0f;
    float m5r[3] = {0.0f, 0.0f, 0.0f};
    __syncthreads();   // full-CTA: weights visible to both halves

    for (int t = 0; t < TSTEPS; t++) {
        // ======== conv1 (1->16, k=7): 128 threads/sample, 3 outputs each ========
        {
            const float* xr = xb + (t & 1) * 32;
            if (hwarp == 0 && lane < L0 && t + 1 < TSTEPS)
                xb[((t + 1) & 1) * 32 + lane] =
                    __ldg(&x[b * (L0 * TSTEPS) + lane * TSTEPS + t + 1]);
            #pragma unroll
            for (int it = 0; it < 3; it++) {
                int idx = htid + it * 128;
                int l = idx >> 4, co = idx & 15;
                float acc = sb1[co];
                #pragma unroll
                for (int k = 0; k < K1; k++)
                    acc = fmaf(sw1t[k * C1 + co], xr[l + k], acc);
                float mn = lif_new_mem(m1r[it], acc);
                m1r[it] = mn;
                s1buf[idx] = (mn > 1.0f) ? 1.0f : 0.0f;
            }
        }
        barh(barid);   // S1

        // ======== conv2 (16->32, k=5): co=lane, 5 l per thread ========
        {
            u64 acc[5];
            u64 binit = pack2(b2r, 0.0f);
            #pragma unroll
            for (int q = 0; q < 5; q++) acc[q] = binit;
            #pragma unroll 2
            for (int p = 0; p < 8; p++) {
                u64 w[K2];
                #pragma unroll
                for (int k = 0; k < K2; k++)
                    w[k] = lds64(sw2p + ((p * K2 + k) * C2 + lane) * 2);
                const float* sp = s1buf + l02 * C1 + 2 * p;
                #pragma unroll
                for (int d = 0; d < 9; d++) {
                    u64 sv = lds64(sp + d * C1);
                    #pragma unroll
                    for (int k = 0; k < K2; k++) {
                        int q = d - k;
                        if (q >= 0 && q < 5) acc[q] = ffma2(w[k], sv, acc[q]);
                    }
                }
            }
            #pragma unroll
            for (int q = 0; q < 5; q++) {
                float lo, hi; unpack2(acc[q], lo, hi);
                float h = __fadd_rn(lo, hi);
                float mn = lif_new_mem(m2r[q], h);
                m2r[q] = mn;
                s2buf[(l02 + q) * C2 + lane] = (mn > 1.0f) ? 1.0f : 0.0f;
            }
        }
        barh(barid);   // S2

        // ======== conv3 (32->64, k=3): co3, 9 l per thread ========
        {
            u64 acc[9];
            u64 binit = pack2(b3r, 0.0f);
            #pragma unroll
            for (int q = 0; q < 9; q++) acc[q] = binit;
            #pragma unroll 4
            for (int p = 0; p < 16; p++) {
                u64 w[K3];
                #pragma unroll
                for (int k = 0; k < K3; k++)
                    w[k] = lds64(sw3p + ((p * K3 + k) * C3 + co3) * 2);
                const float* sp = s2buf + l03 * C2 + 2 * p;
                #pragma unroll
                for (int d = 0; d < 11; d++) {
                    u64 sv = lds64(sp + d * C2);
                    #pragma unroll
                    for (int k = 0; k < K3; k++) {
                        int q = d - k;
                        if (q >= 0 && q < 9) acc[q] = ffma2(w[k], sv, acc[q]);
                    }
                }
            }
            unsigned bits = 0;
            #pragma unroll
            for (int q = 0; q < 9; q++) {
                float lo, hi; unpack2(acc[q], lo, hi);
                float h = __fadd_rn(lo, hi);
                float mn = lif_new_mem(m3r[q], h);
                m3r[q] = mn;
                if (mn > 1.0f) bits |= 1u << q;
            }
            mkbuf[T3 * 64 + co3] = bits;   // exclusive store, no atomics
        }
        barh(barid);   // S3

        // ======== build active-index list (one warp per half) ========
        if (hwarp == 1) {
            int r0 = 2 * lane, r1 = 2 * lane + 1;
            unsigned m0 = mkbuf[r0] | (mkbuf[64 + r0] << 9);   // 18 bits, l ascending
            unsigned m1 = mkbuf[r1] | (mkbuf[64 + r1] << 9);
            int cnt = __popc(m0) + __popc(m1);
            int pos = cnt;
            #pragma unroll
            for (int o = 1; o < 32; o <<= 1) {
                int v = __shfl_up_sync(0xffffffff, pos, o);
                if (lane >= o) pos += v;
            }
            if (lane == 31) *nact = pos;
            unsigned short* ap = act + (pos - cnt);
            int base0 = r0 * L3;
            while (m0) {
                int l = __ffs(m0) - 1; m0 &= m0 - 1;
                *ap++ = (unsigned short)(base0 + l);
            }
            int base1 = r1 * L3;
            while (m1) {
                int l = __ffs(m1) - 1; m1 &= m1 - 1;
                *ap++ = (unsigned short)(base1 + l);
            }
        }
        barh(barid);   // S3b

        // ======== fc1 (1152->256): 128 threads/sample, 2 outputs each ========
        {
            const int na = *nact;
            u64 acc = __ldg((const u64*)(fb1 + 2 * htid));
            const char* base = (const char*)(g_fw1T + 2 * htid);
            const u64* actq = (const u64*)act;
            int a = 0;
            for (; a + 4 <= na; a += 4) {
                u64 four = actq[a >> 2];
                unsigned i0 = (unsigned)(four & 0xFFFFu);
                unsigned i1 = (unsigned)((four >> 16) & 0xFFFFu);
                unsigned i2 = (unsigned)((four >> 32) & 0xFFFFu);
                unsigned i3 = (unsigned)(four >> 48);
                u64 v0 = __ldg((const u64*)(base + i0 * (H1 * 4)));
                u64 v1 = __ldg((const u64*)(base + i1 * (H1 * 4)));
                u64 v2 = __ldg((const u64*)(base + i2 * (H1 * 4)));
                u64 v3 = __ldg((const u64*)(base + i3 * (H1 * 4)));
                acc = fadd2(acc, v0);
                acc = fadd2(acc, v1);
                acc = fadd2(acc, v2);
                acc = fadd2(acc, v3);
            }
            for (; a < na; a++) {
                unsigned i0 = act[a];
                acc = fadd2(acc, __ldg((const u64*)(base + i0 * (H1 * 4))));
            }
            float lo, hi; unpack2(acc, lo, hi);
            float mn0 = lif_new_mem(m4a, lo);
            float mn1 = lif_new_mem(m4b, hi);
            m4a = mn0; m4b = mn1;
            *(u64*)(s4buf + 2 * htid) =
                pack2((mn0 > 1.0f) ? 1.0f : 0.0f, (mn1 > 1.0f) ? 1.0f : 0.0f);
        }
        barh(barid);   // S4

        // ======== fc2 (256->10) + output ========
        {
            #pragma unroll
            for (int i = 0; i < 3; i++) {
                int j = hwarp + 4 * i;
                if (j < NC) {
                    float acc = 0.0f;
                    #pragma unroll
                    for (int q = 0; q < 8; q++) {
                        int ii = lane + 32 * q;
                        acc = fmaf(__ldg(&fw2[j * H1 + ii]), s4buf[ii], acc);
                    }
                    #pragma unroll
                    for (int o = 16; o > 0; o >>= 1)
                        acc += __shfl_down_sync(0xffffffff, acc, o);
                    if (lane == 0) {
                        acc += __ldg(&fb2[j]);
                        float mn = lif_new_mem(m5r[i], acc);
                        m5r[i] = mn;
                        out[(t * BATCH + b) * NC + j] = (mn > 1.0f) ? 1.0f : 0.0f;
                    }
                }
            }
        }
        // no trailing barrier: fc2 reads only s4buf/fw2; s4's next writer (fc1)
        // is four barriers away; next conv1 writes s1/xb(other buf) whose
        // readers are behind S1.
    }
}

extern "C" void kernel_launch(void* const* d_in, const int* in_sizes, int n_in,
                              void* d_out, int out_size) {
    const float* x   = (const float*)d_in[0];
    const float* w1  = (const float*)d_in[1];
    const float* b1  = (const float*)d_in[2];
    const float* w2  = (const float*)d_in[3];
    const float* b2  = (const float*)d_in[4];
    const float* w3  = (const float*)d_in[5];
    const float* b3  = (const float*)d_in[6];
    const float* fw1 = (const float*)d_in[7];
    const float* fb1 = (const float*)d_in[8];
    const float* fw2 = (const float*)d_in[9];
    const float* fb2 = (const float*)d_in[10];
    float* out = (float*)d_out;

    cudaFuncSetAttribute(snn_kernel, cudaFuncAttributeMaxDynamicSharedMemorySize, SMEM_BYTES);

    transpose_fw1_kernel<<<(H1 * F1 + 255) / 256, 256>>>(fw1);
    snn_kernel<<<BATCH / 2, NTHREADS, SMEM_BYTES>>>(x, w1, b1, w2, b2, w3, b3,
                                                    fb1, fw2, fb2, out);
}